// round 3
// baseline (speedup 1.0000x reference)
#include <cuda_runtime.h>
#include <math.h>

#define NN 500000
#define EE 16000000
#define TB 256

// ---- single aligned scratch blob (no allocation; offsets all 16B-aligned) --
#define OFF_COUNTS 0ULL                      // int[NN]
#define OFF_ROW    2000000ULL                // int[NN+1]
#define OFF_CUR    4000128ULL                // int[NN]
#define OFF_DIS    6000128ULL                // float[NN]
#define OFF_BSUM   8000128ULL                // int[1024]
#define OFF_BOFF   8004224ULL                // int[1024]
#define OFF_CSR    8008320ULL                // int[EE]
#define OFF_H      72008320ULL               // float[NN*16]
#define OFF_G      104008320ULL              // float[NN*16]
#define OFF_H3     136008320ULL              // float[NN*4]
#define SCRATCH_BYTES 144008320ULL

__device__ __align__(128) unsigned char g_scratch[SCRATCH_BYTES];
__device__ int g_is64;   // 1 if edge_index is int64, 0 if int32

__device__ __forceinline__ int*   sc_counts() { return (int*)  (g_scratch + OFF_COUNTS); }
__device__ __forceinline__ int*   sc_row()    { return (int*)  (g_scratch + OFF_ROW); }
__device__ __forceinline__ int*   sc_cur()    { return (int*)  (g_scratch + OFF_CUR); }
__device__ __forceinline__ float* sc_dis()    { return (float*)(g_scratch + OFF_DIS); }
__device__ __forceinline__ int*   sc_bsum()   { return (int*)  (g_scratch + OFF_BSUM); }
__device__ __forceinline__ int*   sc_boff()   { return (int*)  (g_scratch + OFF_BOFF); }
__device__ __forceinline__ int*   sc_csr()    { return (int*)  (g_scratch + OFF_CSR); }
__device__ __forceinline__ float* sc_h()      { return (float*)(g_scratch + OFF_H); }
__device__ __forceinline__ float* sc_g()      { return (float*)(g_scratch + OFF_G); }
__device__ __forceinline__ float* sc_h3()     { return (float*)(g_scratch + OFF_H3); }

// ------------- dtype probe: int64 little-endian small values => odd words 0 --
__global__ void k_probe(const int* __restrict__ ei32) {
    if (blockIdx.x == 0 && threadIdx.x == 0) {
        int all_zero = 1;
        #pragma unroll 1
        for (int k = 0; k < 64; k++) {
            if (ei32[2 * k + 1] != 0) { all_zero = 0; break; }
        }
        g_is64 = all_zero;
    }
}

__device__ __forceinline__ void load_edge(const void* eiv, int E, int e,
                                          int is64, int& s, int& d) {
    if (is64) {
        const long long* ei = (const long long*)eiv;
        long long sl = ei[e];
        long long dl = ei[(size_t)E + e];
        s = (int)sl; d = (int)dl;
        if ((unsigned long long)sl >= (unsigned long long)NN ||
            (unsigned long long)dl >= (unsigned long long)NN) { s = -1; d = -1; }
    } else {
        const int* ei = (const int*)eiv;
        s = ei[e];
        d = ei[(size_t)E + e];
        if ((unsigned)s >= (unsigned)NN || (unsigned)d >= (unsigned)NN) { s = -1; d = -1; }
    }
}

// ---------------- CSR build -------------------------------------------------
__global__ void k_zero(int n) {
    int i = blockIdx.x * blockDim.x + threadIdx.x;
    if (i < n) sc_counts()[i] = 0;
}

__global__ void k_hist(const void* __restrict__ eiv, int E) {
    int e = blockIdx.x * blockDim.x + threadIdx.x;
    if (e >= E) return;
    int is64 = g_is64;
    int s, d;
    load_edge(eiv, E, e, is64, s, d);
    if (d >= 0) atomicAdd(&sc_counts()[d], 1);
}

__global__ void k_scan_block(int n) {
    __shared__ int sh[1024];
    int t = threadIdx.x;
    int i = blockIdx.x * 1024 + t;
    int v = (i < n) ? sc_counts()[i] : 0;
    sh[t] = v;
    __syncthreads();
    for (int off = 1; off < 1024; off <<= 1) {
        int a = (t >= off) ? sh[t - off] : 0;
        __syncthreads();
        sh[t] += a;
        __syncthreads();
    }
    if (i < n) sc_row()[i] = sh[t] - v;            // exclusive within block
    if (t == 1023) sc_bsum()[blockIdx.x] = sh[1023];
}

__global__ void k_scan_top(int nb) {
    __shared__ int sh[1024];
    int t = threadIdx.x;
    int v = (t < nb) ? sc_bsum()[t] : 0;
    sh[t] = v;
    __syncthreads();
    for (int off = 1; off < 1024; off <<= 1) {
        int a = (t >= off) ? sh[t - off] : 0;
        __syncthreads();
        sh[t] += a;
        __syncthreads();
    }
    sc_boff()[t] = sh[t] - v;                      // exclusive block offsets
}

__global__ void k_finish(int n) {
    int i = blockIdx.x * blockDim.x + threadIdx.x;
    if (i < n) {
        int r = sc_row()[i] + sc_boff()[i >> 10];
        sc_row()[i] = r;
        sc_cur()[i] = r;
        sc_dis()[i] = rsqrtf((float)(sc_counts()[i] + 1));  // +1 self-loop
    }
    if (blockIdx.x == 0 && threadIdx.x == 0) {
        // row[n] set after this kernel by k_set_total (needs final row[n-1])
    }
}

__global__ void k_set_total(int n) {
    if (blockIdx.x == 0 && threadIdx.x == 0)
        sc_row()[n] = sc_row()[n - 1] + sc_counts()[n - 1];
}

__global__ void k_scatter(const void* __restrict__ eiv, int E) {
    int e = blockIdx.x * blockDim.x + threadIdx.x;
    if (e >= E) return;
    int is64 = g_is64;
    int s, d;
    load_edge(eiv, E, e, is64, s, d);
    if (d >= 0) {
        int p = atomicAdd(&sc_cur()[d], 1);
        sc_csr()[p] = s;
    }
}

// ---------------- layer 1 transform: h1' = (x @ W1) * dis -------------------
__global__ void __launch_bounds__(TB)
k_t1(const float* __restrict__ x, const float* __restrict__ W, int n) {
    __shared__ float Ws[225];
    for (int t = threadIdx.x; t < 225; t += blockDim.x) Ws[t] = W[t];
    __syncthreads();
    int i = blockIdx.x * blockDim.x + threadIdx.x;
    if (i >= n) return;
    float xv[15];
    #pragma unroll
    for (int k = 0; k < 15; k++) xv[k] = x[(size_t)i * 15 + k];
    float di = sc_dis()[i];
    float o[16];
    o[15] = 0.f;
    #pragma unroll
    for (int j = 0; j < 15; j++) {
        float s = 0.f;
        #pragma unroll
        for (int k = 0; k < 15; k++) s += xv[k] * Ws[k * 15 + j];
        o[j] = s * di;
    }
    float4* outp = (float4*)(sc_h() + (size_t)i * 16);
    outp[0] = make_float4(o[0],  o[1],  o[2],  o[3]);
    outp[1] = make_float4(o[4],  o[5],  o[6],  o[7]);
    outp[2] = make_float4(o[8],  o[9],  o[10], o[11]);
    outp[3] = make_float4(o[12], o[13], o[14], o[15]);
}

// ------- aggregation + fused next-layer transform ----------------------------
template <int FOUT>
__global__ void __launch_bounds__(TB)
k_agg_fused(const float* __restrict__ bias, const float* __restrict__ Wn, int n) {
    __shared__ float Ws[15 * FOUT];
    __shared__ float bs[15];
    for (int t = threadIdx.x; t < 15 * FOUT; t += blockDim.x) Ws[t] = Wn[t];
    if (threadIdx.x < 15) bs[threadIdx.x] = bias[threadIdx.x];
    __syncthreads();

    int i = blockIdx.x * blockDim.x + threadIdx.x;
    if (i >= n) return;

    const float4* hb = (const float4*)((FOUT == 15) ? sc_h() : sc_g());
    const int* csr = sc_csr();

    float4 a0 = make_float4(0.f, 0.f, 0.f, 0.f);
    float4 a1 = a0, a2 = a0, a3 = a0;

    int beg = sc_row()[i], end = sc_row()[i + 1];
    for (int j = beg; j < end; j++) {
        int s = csr[j];
        const float4* p = hb + (size_t)s * 4;
        float4 v0 = p[0], v1 = p[1], v2 = p[2], v3 = p[3];
        a0.x += v0.x; a0.y += v0.y; a0.z += v0.z; a0.w += v0.w;
        a1.x += v1.x; a1.y += v1.y; a1.z += v1.z; a1.w += v1.w;
        a2.x += v2.x; a2.y += v2.y; a2.z += v2.z; a2.w += v2.w;
        a3.x += v3.x; a3.y += v3.y; a3.z += v3.z; a3.w += v3.w;
    }
    {   // self-loop
        const float4* p = hb + (size_t)i * 4;
        float4 v0 = p[0], v1 = p[1], v2 = p[2], v3 = p[3];
        a0.x += v0.x; a0.y += v0.y; a0.z += v0.z; a0.w += v0.w;
        a1.x += v1.x; a1.y += v1.y; a1.z += v1.z; a1.w += v1.w;
        a2.x += v2.x; a2.y += v2.y; a2.z += v2.z; a2.w += v2.w;
        a3.x += v3.x; a3.y += v3.y; a3.z += v3.z; a3.w += v3.w;
    }

    float acc[16];
    acc[0]=a0.x; acc[1]=a0.y; acc[2]=a0.z; acc[3]=a0.w;
    acc[4]=a1.x; acc[5]=a1.y; acc[6]=a1.z; acc[7]=a1.w;
    acc[8]=a2.x; acc[9]=a2.y; acc[10]=a2.z; acc[11]=a2.w;
    acc[12]=a3.x; acc[13]=a3.y; acc[14]=a3.z; acc[15]=a3.w;

    float di = sc_dis()[i];
    float y[15];
    #pragma unroll
    for (int k = 0; k < 15; k++)
        y[k] = fmaxf(acc[k] * di + bs[k], 0.f);

    if (FOUT == 15) {
        float o[16];
        o[15] = 0.f;
        #pragma unroll
        for (int j = 0; j < 15; j++) {
            float s = 0.f;
            #pragma unroll
            for (int k = 0; k < 15; k++) s += y[k] * Ws[k * 15 + j];
            o[j] = s * di;
        }
        float4* outp = (float4*)(sc_g() + (size_t)i * 16);
        outp[0] = make_float4(o[0],  o[1],  o[2],  o[3]);
        outp[1] = make_float4(o[4],  o[5],  o[6],  o[7]);
        outp[2] = make_float4(o[8],  o[9],  o[10], o[11]);
        outp[3] = make_float4(o[12], o[13], o[14], o[15]);
    } else {
        float o[4];
        #pragma unroll
        for (int j = 0; j < 4; j++) {
            float s = 0.f;
            #pragma unroll
            for (int k = 0; k < 15; k++) s += y[k] * Ws[k * 4 + j];
            o[j] = s * di;
        }
        ((float4*)sc_h3())[i] = make_float4(o[0], o[1], o[2], o[3]);
    }
}

// ---------------- final layer aggregation ------------------------------------
__global__ void __launch_bounds__(TB)
k_agg_final(const float* __restrict__ bias, float* __restrict__ out, int n) {
    int i = blockIdx.x * blockDim.x + threadIdx.x;
    if (i >= n) return;
    const float4* hb = (const float4*)sc_h3();
    const int* csr = sc_csr();
    float4 a = make_float4(0.f, 0.f, 0.f, 0.f);
    int beg = sc_row()[i], end = sc_row()[i + 1];
    for (int j = beg; j < end; j++) {
        int s = csr[j];
        float4 v = hb[s];
        a.x += v.x; a.y += v.y; a.z += v.z; a.w += v.w;
    }
    float4 v = hb[i];   // self-loop
    a.x += v.x; a.y += v.y; a.z += v.z; a.w += v.w;
    float di = sc_dis()[i];
    float b0 = bias[0], b1 = bias[1], b2 = bias[2], b3 = bias[3];
    ((float4*)out)[i] = make_float4(a.x * di + b0, a.y * di + b1,
                                    a.z * di + b2, a.w * di + b3);
}

// ---------------- launch ------------------------------------------------------
extern "C" void kernel_launch(void* const* d_in, const int* in_sizes, int n_in,
                              void* d_out, int out_size) {
    // Identify inputs by element count (robust to metadata ordering):
    const float* x = nullptr; const void* ei = nullptr;
    const float* W1 = nullptr; const float* W2 = nullptr;
    const float* b1 = nullptr; const float* b2 = nullptr;
    const float* W3 = nullptr; const float* b3 = nullptr;
    long long E_ll = 0;
    for (int i = 0; i < n_in; i++) {
        long long sz = in_sizes[i];
        if (sz == 7500000)            x = (const float*)d_in[i];
        else if (sz == 32000000)    { ei = d_in[i]; E_ll = sz / 2; }
        else if (sz == 225)         { if (!W1) W1 = (const float*)d_in[i]; else W2 = (const float*)d_in[i]; }
        else if (sz == 15)          { if (!b1) b1 = (const float*)d_in[i]; else b2 = (const float*)d_in[i]; }
        else if (sz == 60)            W3 = (const float*)d_in[i];
        else if (sz == 4)             b3 = (const float*)d_in[i];
    }
    if (!x)  x  = (const float*)d_in[0];
    if (!ei) { ei = d_in[1]; E_ll = in_sizes[1] / 2; }
    if (!W1) W1 = (const float*)d_in[3];
    if (!b1) b1 = (const float*)d_in[4];
    if (!W2) W2 = (const float*)d_in[5];
    if (!b2) b2 = (const float*)d_in[6];
    if (!W3) W3 = (const float*)d_in[7];
    if (!b3) b3 = (const float*)d_in[8];

    float* out = (float*)d_out;
    int n = NN;
    int E = (int)E_ll;

    int gbN = (n + TB - 1) / TB;
    int gbE = (E + TB - 1) / TB;
    int nb  = (n + 1023) / 1024;

    k_probe<<<1, 32>>>((const int*)ei);
    k_zero<<<gbN, TB>>>(n);
    k_hist<<<gbE, TB>>>(ei, E);
    k_scan_block<<<nb, 1024>>>(n);
    k_scan_top<<<1, 1024>>>(nb);
    k_finish<<<gbN, TB>>>(n);
    k_set_total<<<1, 32>>>(n);
    k_scatter<<<gbE, TB>>>(ei, E);

    k_t1<<<gbN, TB>>>(x, W1, n);
    k_agg_fused<15><<<gbN, TB>>>(b1, W2, n);
    k_agg_fused<4><<<gbN, TB>>>(b2, W3, n);
    k_agg_final<<<gbN, TB>>>(b3, out, n);
}

// round 4
// speedup vs baseline: 1.1747x; 1.1747x over previous
#include <cuda_runtime.h>
#include <math.h>

#define NN 500000
#define EE 16000000
#define TB 256

// ---- single aligned scratch blob (no allocation; offsets all 16B-aligned) --
#define OFF_COUNTS 0ULL                      // int[NN]
#define OFF_ROW    2000000ULL                // int[NN+1]
#define OFF_CUR    4000128ULL                // int[NN]
#define OFF_DIS    6000128ULL                // float[NN]
#define OFF_BSUM   8000128ULL                // int[1024]
#define OFF_BOFF   8004224ULL                // int[1024]
#define OFF_CSR    8008320ULL                // int[EE]
#define OFF_H      72008320ULL               // float[NN*16]
#define OFF_G      104008320ULL              // float[NN*16]
#define OFF_H3     136008320ULL              // float[NN*4]
#define SCRATCH_BYTES 144008320ULL

__device__ __align__(128) unsigned char g_scratch[SCRATCH_BYTES];
__device__ int g_is64;   // 1 if edge_index is int64, 0 if int32

__device__ __forceinline__ int*   sc_counts() { return (int*)  (g_scratch + OFF_COUNTS); }
__device__ __forceinline__ int*   sc_row()    { return (int*)  (g_scratch + OFF_ROW); }
__device__ __forceinline__ int*   sc_cur()    { return (int*)  (g_scratch + OFF_CUR); }
__device__ __forceinline__ float* sc_dis()    { return (float*)(g_scratch + OFF_DIS); }
__device__ __forceinline__ int*   sc_bsum()   { return (int*)  (g_scratch + OFF_BSUM); }
__device__ __forceinline__ int*   sc_boff()   { return (int*)  (g_scratch + OFF_BOFF); }
__device__ __forceinline__ int*   sc_csr()    { return (int*)  (g_scratch + OFF_CSR); }
__device__ __forceinline__ float* sc_h()      { return (float*)(g_scratch + OFF_H); }
__device__ __forceinline__ float* sc_g()      { return (float*)(g_scratch + OFF_G); }
__device__ __forceinline__ float* sc_h3()     { return (float*)(g_scratch + OFF_H3); }

// ------------- dtype probe: int64 little-endian small values => odd words 0 --
__global__ void k_probe(const int* __restrict__ ei32) {
    if (blockIdx.x == 0 && threadIdx.x == 0) {
        int all_zero = 1;
        #pragma unroll 1
        for (int k = 0; k < 64; k++) {
            if (ei32[2 * k + 1] != 0) { all_zero = 0; break; }
        }
        g_is64 = all_zero;
    }
}

__device__ __forceinline__ void load_edge(const void* eiv, int E, int e,
                                          int is64, int& s, int& d) {
    if (is64) {
        const long long* ei = (const long long*)eiv;
        long long sl = __ldcs(&ei[e]);
        long long dl = __ldcs(&ei[(size_t)E + e]);
        s = (int)sl; d = (int)dl;
        if ((unsigned long long)sl >= (unsigned long long)NN ||
            (unsigned long long)dl >= (unsigned long long)NN) { s = -1; d = -1; }
    } else {
        const int* ei = (const int*)eiv;
        s = __ldcs(&ei[e]);
        d = __ldcs(&ei[(size_t)E + e]);
        if ((unsigned)s >= (unsigned)NN || (unsigned)d >= (unsigned)NN) { s = -1; d = -1; }
    }
}

// ---------------- CSR build -------------------------------------------------
__global__ void k_zero(int n) {
    int i = blockIdx.x * blockDim.x + threadIdx.x;
    if (i < n) sc_counts()[i] = 0;
}

__global__ void k_hist(const void* __restrict__ eiv, int E) {
    int e = blockIdx.x * blockDim.x + threadIdx.x;
    if (e >= E) return;
    int is64 = g_is64;
    int s, d;
    load_edge(eiv, E, e, is64, s, d);
    if (d >= 0) atomicAdd(&sc_counts()[d], 1);
}

__global__ void k_scan_block(int n) {
    __shared__ int sh[1024];
    int t = threadIdx.x;
    int i = blockIdx.x * 1024 + t;
    int v = (i < n) ? sc_counts()[i] : 0;
    sh[t] = v;
    __syncthreads();
    for (int off = 1; off < 1024; off <<= 1) {
        int a = (t >= off) ? sh[t - off] : 0;
        __syncthreads();
        sh[t] += a;
        __syncthreads();
    }
    if (i < n) sc_row()[i] = sh[t] - v;            // exclusive within block
    if (t == 1023) sc_bsum()[blockIdx.x] = sh[1023];
}

__global__ void k_scan_top(int nb, int n) {
    __shared__ int sh[1024];
    int t = threadIdx.x;
    int v = (t < nb) ? sc_bsum()[t] : 0;
    sh[t] = v;
    __syncthreads();
    for (int off = 1; off < 1024; off <<= 1) {
        int a = (t >= off) ? sh[t - off] : 0;
        __syncthreads();
        sh[t] += a;
        __syncthreads();
    }
    sc_boff()[t] = sh[t] - v;                      // exclusive block offsets
    if (t == 1023) sc_row()[n] = sh[1023];         // total valid edges
}

__global__ void k_finish(int n) {
    int i = blockIdx.x * blockDim.x + threadIdx.x;
    if (i < n) {
        int r = sc_row()[i] + sc_boff()[i >> 10];
        sc_row()[i] = r;
        sc_cur()[i] = r;
        sc_dis()[i] = rsqrtf((float)(sc_counts()[i] + 1));  // +1 self-loop
    }
}

__global__ void k_scatter(const void* __restrict__ eiv, int E) {
    int e = blockIdx.x * blockDim.x + threadIdx.x;
    if (e >= E) return;
    int is64 = g_is64;
    int s, d;
    load_edge(eiv, E, e, is64, s, d);
    if (d >= 0) {
        int p = atomicAdd(&sc_cur()[d], 1);
        sc_csr()[p] = s;
    }
}

// ---------------- layer 1 transform: h1' = (x @ W1) * dis -------------------
__global__ void __launch_bounds__(TB)
k_t1(const float* __restrict__ x, const float* __restrict__ W, int n) {
    __shared__ float Ws[225];
    for (int t = threadIdx.x; t < 225; t += blockDim.x) Ws[t] = W[t];
    __syncthreads();
    int i = blockIdx.x * blockDim.x + threadIdx.x;
    if (i >= n) return;
    float xv[15];
    #pragma unroll
    for (int k = 0; k < 15; k++) xv[k] = __ldcs(&x[(size_t)i * 15 + k]);
    float di = sc_dis()[i];
    float o[16];
    o[15] = 0.f;
    #pragma unroll
    for (int j = 0; j < 15; j++) {
        float s = 0.f;
        #pragma unroll
        for (int k = 0; k < 15; k++) s += xv[k] * Ws[k * 15 + j];
        o[j] = s * di;
    }
    float4* outp = (float4*)(sc_h() + (size_t)i * 16);
    outp[0] = make_float4(o[0],  o[1],  o[2],  o[3]);
    outp[1] = make_float4(o[4],  o[5],  o[6],  o[7]);
    outp[2] = make_float4(o[8],  o[9],  o[10], o[11]);
    outp[3] = make_float4(o[12], o[13], o[14], o[15]);
}

// ------- 4-lanes-per-node aggregation + fused next-layer transform ----------
// Lane c of each 4-lane group accumulates float4 chunk c of the 16-float row,
// so a warp's gather LDG.128 serves 8 edges with 64B-contiguous lanes
// (~1 L1 wavefront per edge instead of ~4).
// FOUT=15: reads h, y = relu(dis*(sum+self)+b), writes g = (y@W)*dis
// FOUT=4 : reads g, y = relu(dis*(sum+self)+b), writes h3 = (y@W)*dis
template <int FOUT>
__global__ void __launch_bounds__(TB)
k_agg4(const float* __restrict__ bias, const float* __restrict__ Wn, int n) {
    __shared__ float Ws[16 * 16];        // padded weights, zero-filled
    __shared__ float bs[16];
    __shared__ float ysh[TB / 4][17];    // per-group y, padded stride (no bank conflicts)

    for (int t = threadIdx.x; t < 256; t += blockDim.x) Ws[t] = 0.f;
    if (threadIdx.x < 16) bs[threadIdx.x] = 0.f;
    __syncthreads();
    if (FOUT == 15) {
        // Wn is 15x15 row-major -> Ws[k*16 + j]
        for (int t = threadIdx.x; t < 225; t += blockDim.x)
            Ws[(t / 15) * 16 + (t % 15)] = Wn[t];
    } else {
        // Wn is 15x4 row-major -> Ws[k*4 + j] (first 60 slots)
        for (int t = threadIdx.x; t < 60; t += blockDim.x) Ws[t] = Wn[t];
    }
    if (threadIdx.x < 15) bs[threadIdx.x] = bias[threadIdx.x];
    __syncthreads();

    int gidx = threadIdx.x >> 2;                 // group within block
    int c    = threadIdx.x & 3;                  // chunk id
    int i    = blockIdx.x * (TB / 4) + gidx;     // node id

    const float4* hb = (const float4*)((FOUT == 15) ? sc_h() : sc_g());
    const int* csr = sc_csr();
    float di = 0.f;

    if (i < n) {
        float4 a = make_float4(0.f, 0.f, 0.f, 0.f);
        int beg = sc_row()[i], end = sc_row()[i + 1];
        for (int j = beg; j < end; j++) {
            int s = __ldcs(&csr[j]);             // broadcast across the 4 lanes
            float4 v = hb[(size_t)s * 4 + c];
            a.x += v.x; a.y += v.y; a.z += v.z; a.w += v.w;
        }
        float4 v = hb[(size_t)i * 4 + c];        // self-loop
        a.x += v.x; a.y += v.y; a.z += v.z; a.w += v.w;

        di = sc_dis()[i];
        int k0 = c * 4;
        ysh[gidx][k0 + 0] = fmaxf(a.x * di + bs[k0 + 0], 0.f);
        ysh[gidx][k0 + 1] = fmaxf(a.y * di + bs[k0 + 1], 0.f);
        ysh[gidx][k0 + 2] = fmaxf(a.z * di + bs[k0 + 2], 0.f);
        ysh[gidx][k0 + 3] = fmaxf(a.w * di + bs[k0 + 3], 0.f);
    }
    __syncthreads();

    if (i < n) {
        if (FOUT == 15) {
            // lane c computes output columns 4c..4c+3 (col 15 pad -> 0)
            int j0 = c * 4;
            float o0 = 0.f, o1 = 0.f, o2 = 0.f, o3 = 0.f;
            #pragma unroll
            for (int k = 0; k < 15; k++) {
                float yk = ysh[gidx][k];
                o0 += yk * Ws[k * 16 + j0 + 0];
                o1 += yk * Ws[k * 16 + j0 + 1];
                o2 += yk * Ws[k * 16 + j0 + 2];
                o3 += yk * Ws[k * 16 + j0 + 3];
            }
            ((float4*)sc_g())[(size_t)i * 4 + c] =
                make_float4(o0 * di, o1 * di, o2 * di, o3 * di);
        } else {
            // lane c computes output column c of the 15x4 GEMM
            float o = 0.f;
            #pragma unroll
            for (int k = 0; k < 15; k++)
                o += ysh[gidx][k] * Ws[k * 4 + c];
            sc_h3()[(size_t)i * 4 + c] = o * di;
        }
    }
}

// ---------------- final layer aggregation ------------------------------------
__global__ void __launch_bounds__(TB)
k_agg_final(const float* __restrict__ bias, float* __restrict__ out, int n) {
    int i = blockIdx.x * blockDim.x + threadIdx.x;
    if (i >= n) return;
    const float4* hb = (const float4*)sc_h3();
    const int* csr = sc_csr();
    float4 a = make_float4(0.f, 0.f, 0.f, 0.f);
    int beg = sc_row()[i], end = sc_row()[i + 1];
    for (int j = beg; j < end; j++) {
        int s = __ldcs(&csr[j]);
        float4 v = hb[s];
        a.x += v.x; a.y += v.y; a.z += v.z; a.w += v.w;
    }
    float4 v = hb[i];   // self-loop
    a.x += v.x; a.y += v.y; a.z += v.z; a.w += v.w;
    float di = sc_dis()[i];
    float b0 = bias[0], b1 = bias[1], b2 = bias[2], b3 = bias[3];
    ((float4*)out)[i] = make_float4(a.x * di + b0, a.y * di + b1,
                                    a.z * di + b2, a.w * di + b3);
}

// ---------------- launch ------------------------------------------------------
extern "C" void kernel_launch(void* const* d_in, const int* in_sizes, int n_in,
                              void* d_out, int out_size) {
    const float* x = nullptr; const void* ei = nullptr;
    const float* W1 = nullptr; const float* W2 = nullptr;
    const float* b1 = nullptr; const float* b2 = nullptr;
    const float* W3 = nullptr; const float* b3 = nullptr;
    long long E_ll = 0;
    for (int i = 0; i < n_in; i++) {
        long long sz = in_sizes[i];
        if (sz == 7500000)            x = (const float*)d_in[i];
        else if (sz == 32000000)    { ei = d_in[i]; E_ll = sz / 2; }
        else if (sz == 225)         { if (!W1) W1 = (const float*)d_in[i]; else W2 = (const float*)d_in[i]; }
        else if (sz == 15)          { if (!b1) b1 = (const float*)d_in[i]; else b2 = (const float*)d_in[i]; }
        else if (sz == 60)            W3 = (const float*)d_in[i];
        else if (sz == 4)             b3 = (const float*)d_in[i];
    }
    if (!x)  x  = (const float*)d_in[0];
    if (!ei) { ei = d_in[1]; E_ll = in_sizes[1] / 2; }
    if (!W1) W1 = (const float*)d_in[3];
    if (!b1) b1 = (const float*)d_in[4];
    if (!W2) W2 = (const float*)d_in[5];
    if (!b2) b2 = (const float*)d_in[6];
    if (!W3) W3 = (const float*)d_in[7];
    if (!b3) b3 = (const float*)d_in[8];

    float* out = (float*)d_out;
    int n = NN;
    int E = (int)E_ll;

    int gbN  = (n + TB - 1) / TB;
    int gbE  = (E + TB - 1) / TB;
    int nb   = (n + 1023) / 1024;
    int gbN4 = (n + (TB / 4) - 1) / (TB / 4);   // 4 lanes per node

    k_probe<<<1, 32>>>((const int*)ei);
    k_zero<<<gbN, TB>>>(n);
    k_hist<<<gbE, TB>>>(ei, E);
    k_scan_block<<<nb, 1024>>>(n);
    k_scan_top<<<1, 1024>>>(nb, n);
    k_finish<<<gbN, TB>>>(n);
    k_scatter<<<gbE, TB>>>(ei, E);

    k_t1<<<gbN, TB>>>(x, W1, n);
    k_agg4<15><<<gbN4, TB>>>(b1, W2, n);
    k_agg4<4><<<gbN4, TB>>>(b2, W3, n);
    k_agg_final<<<gbN, TB>>>(b3, out, n);
}

// round 5
// speedup vs baseline: 1.2667x; 1.0783x over previous
#include <cuda_runtime.h>
#include <cuda_fp16.h>
#include <math.h>

#define NN 500000
#define EE 16000000
#define TB 256

// ---- single aligned scratch blob (no allocation; offsets all 128B-aligned) --
#define OFF_COUNTS 0ULL                      // int[NN]
#define OFF_ROW    2000000ULL                // int[NN+1]
#define OFF_CUR    4000128ULL                // int[NN]
#define OFF_DIS    6000128ULL                // float[NN]
#define OFF_BSUM   8000128ULL                // int[1024]
#define OFF_BOFF   8004224ULL                // int[1024]
#define OFF_CSR    8008320ULL                // int[EE]
#define OFF_H      72008320ULL               // half[NN*16]  16MB
#define OFF_G      88008320ULL               // half[NN*16]  16MB
#define OFF_H3     104008320ULL              // float[NN*4]   8MB
#define SCRATCH_BYTES 112008320ULL

__device__ __align__(128) unsigned char g_scratch[SCRATCH_BYTES];
__device__ int g_is64;   // 1 if edge_index is int64, 0 if int32

__device__ __forceinline__ int*    sc_counts() { return (int*)   (g_scratch + OFF_COUNTS); }
__device__ __forceinline__ int*    sc_row()    { return (int*)   (g_scratch + OFF_ROW); }
__device__ __forceinline__ int*    sc_cur()    { return (int*)   (g_scratch + OFF_CUR); }
__device__ __forceinline__ float*  sc_dis()    { return (float*) (g_scratch + OFF_DIS); }
__device__ __forceinline__ int*    sc_bsum()   { return (int*)   (g_scratch + OFF_BSUM); }
__device__ __forceinline__ int*    sc_boff()   { return (int*)   (g_scratch + OFF_BOFF); }
__device__ __forceinline__ int*    sc_csr()    { return (int*)   (g_scratch + OFF_CSR); }
__device__ __forceinline__ __half* sc_h()      { return (__half*)(g_scratch + OFF_H); }
__device__ __forceinline__ __half* sc_g()      { return (__half*)(g_scratch + OFF_G); }
__device__ __forceinline__ float*  sc_h3()     { return (float*) (g_scratch + OFF_H3); }

// ---------------- zero + dtype probe ----------------------------------------
// int64 little-endian node ids < 2^31  =>  every odd 4-byte word is zero.
__global__ void k_zero(const int* __restrict__ ei32, int n) {
    int i = blockIdx.x * blockDim.x + threadIdx.x;
    if (i < n) sc_counts()[i] = 0;
    if (i == 0) {
        int all_zero = 1;
        #pragma unroll 1
        for (int k = 0; k < 64; k++)
            if (ei32[2 * k + 1] != 0) { all_zero = 0; break; }
        g_is64 = all_zero;
    }
}

__device__ __forceinline__ void load_edge(const void* eiv, int E, int e,
                                          int is64, int& s, int& d) {
    if (is64) {
        const long long* ei = (const long long*)eiv;
        long long sl = __ldcs(&ei[e]);
        long long dl = __ldcs(&ei[(size_t)E + e]);
        s = (int)sl; d = (int)dl;
        if ((unsigned long long)sl >= (unsigned long long)NN ||
            (unsigned long long)dl >= (unsigned long long)NN) { s = -1; d = -1; }
    } else {
        const int* ei = (const int*)eiv;
        s = __ldcs(&ei[e]);
        d = __ldcs(&ei[(size_t)E + e]);
        if ((unsigned)s >= (unsigned)NN || (unsigned)d >= (unsigned)NN) { s = -1; d = -1; }
    }
}

// ---------------- CSR build -------------------------------------------------
__global__ void k_hist(const void* __restrict__ eiv, int E) {
    int e = blockIdx.x * blockDim.x + threadIdx.x;
    if (e >= E) return;
    int is64 = g_is64;
    int s, d;
    load_edge(eiv, E, e, is64, s, d);
    if (d >= 0) atomicAdd(&sc_counts()[d], 1);
}

__global__ void k_scan_block(int n) {
    __shared__ int sh[1024];
    int t = threadIdx.x;
    int i = blockIdx.x * 1024 + t;
    int v = (i < n) ? sc_counts()[i] : 0;
    sh[t] = v;
    __syncthreads();
    for (int off = 1; off < 1024; off <<= 1) {
        int a = (t >= off) ? sh[t - off] : 0;
        __syncthreads();
        sh[t] += a;
        __syncthreads();
    }
    if (i < n) sc_row()[i] = sh[t] - v;            // exclusive within block
    if (t == 1023) sc_bsum()[blockIdx.x] = sh[1023];
}

__global__ void k_scan_top(int nb, int n) {
    __shared__ int sh[1024];
    int t = threadIdx.x;
    int v = (t < nb) ? sc_bsum()[t] : 0;
    sh[t] = v;
    __syncthreads();
    for (int off = 1; off < 1024; off <<= 1) {
        int a = (t >= off) ? sh[t - off] : 0;
        __syncthreads();
        sh[t] += a;
        __syncthreads();
    }
    sc_boff()[t] = sh[t] - v;                      // exclusive block offsets
    if (t == 1023) sc_row()[n] = sh[1023];         // total valid edges
}

__global__ void k_finish(int n) {
    int i = blockIdx.x * blockDim.x + threadIdx.x;
    if (i < n) {
        int r = sc_row()[i] + sc_boff()[i >> 10];
        sc_row()[i] = r;
        sc_cur()[i] = r;
        sc_dis()[i] = rsqrtf((float)(sc_counts()[i] + 1));  // +1 self-loop
    }
}

__global__ void k_scatter(const void* __restrict__ eiv, int E) {
    int e = blockIdx.x * blockDim.x + threadIdx.x;
    if (e >= E) return;
    int is64 = g_is64;
    int s, d;
    load_edge(eiv, E, e, is64, s, d);
    if (d >= 0) {
        int p = atomicAdd(&sc_cur()[d], 1);
        sc_csr()[p] = s;
    }
}

// ------------- pack 8 fp32 -> uint4 of 8 halves ------------------------------
__device__ __forceinline__ uint4 pack8(const float* o) {
    __half2 p0 = __floats2half2_rn(o[0], o[1]);
    __half2 p1 = __floats2half2_rn(o[2], o[3]);
    __half2 p2 = __floats2half2_rn(o[4], o[5]);
    __half2 p3 = __floats2half2_rn(o[6], o[7]);
    uint4 u;
    u.x = *(unsigned int*)&p0; u.y = *(unsigned int*)&p1;
    u.z = *(unsigned int*)&p2; u.w = *(unsigned int*)&p3;
    return u;
}

__device__ __forceinline__ void acc8(float* acc, uint4 v) {
    float2 f;
    f = __half22float2(*(__half2*)&v.x); acc[0] += f.x; acc[1] += f.y;
    f = __half22float2(*(__half2*)&v.y); acc[2] += f.x; acc[3] += f.y;
    f = __half22float2(*(__half2*)&v.z); acc[4] += f.x; acc[5] += f.y;
    f = __half22float2(*(__half2*)&v.w); acc[6] += f.x; acc[7] += f.y;
}

// ---------------- layer 1 transform: h1' = (x @ W1) * dis  (fp16 out) -------
__global__ void __launch_bounds__(TB)
k_t1(const float* __restrict__ x, const float* __restrict__ W, int n) {
    __shared__ float Ws[225];
    for (int t = threadIdx.x; t < 225; t += blockDim.x) Ws[t] = W[t];
    __syncthreads();
    int i = blockIdx.x * blockDim.x + threadIdx.x;
    if (i >= n) return;
    float xv[15];
    #pragma unroll
    for (int k = 0; k < 15; k++) xv[k] = __ldcs(&x[(size_t)i * 15 + k]);
    float di = sc_dis()[i];
    float o[16];
    o[15] = 0.f;
    #pragma unroll
    for (int j = 0; j < 15; j++) {
        float s = 0.f;
        #pragma unroll
        for (int k = 0; k < 15; k++) s += xv[k] * Ws[k * 15 + j];
        o[j] = s * di;
    }
    uint4* outp = (uint4*)(sc_h() + (size_t)i * 16);
    outp[0] = pack8(o);
    outp[1] = pack8(o + 8);
}

// ------- 2-lanes-per-node fp16 aggregation + fused next-layer transform -----
// Lane c of each pair loads the 16B uint4 chunk c (8 halves) of the 32B row:
// one LDG.128 serves 16 edges, 1 L2 sector & ~1 L1 wavefront per edge.
// FOUT=15: reads h (fp16), y=relu(dis*(sum+self)+b), writes g=(y@W)*dis (fp16)
// FOUT=4 : reads g (fp16), y=relu(...), writes h3=(y@W)*dis (fp32)
template <int FOUT>
__global__ void __launch_bounds__(TB)
k_agg2(const float* __restrict__ bias, const float* __restrict__ Wn, int n) {
    __shared__ float Ws[16 * 16];
    __shared__ float bs[16];
    __shared__ float ysh[TB / 2][17];

    for (int t = threadIdx.x; t < 256; t += blockDim.x) Ws[t] = 0.f;
    if (threadIdx.x < 16) bs[threadIdx.x] = 0.f;
    __syncthreads();
    if (FOUT == 15) {
        for (int t = threadIdx.x; t < 225; t += blockDim.x)
            Ws[(t / 15) * 16 + (t % 15)] = Wn[t];      // 15x15 -> stride 16
    } else {
        for (int t = threadIdx.x; t < 60; t += blockDim.x) Ws[t] = Wn[t];  // 15x4
    }
    if (threadIdx.x < 15) bs[threadIdx.x] = bias[threadIdx.x];
    __syncthreads();

    int gidx = threadIdx.x >> 1;                 // pair within block
    int c    = threadIdx.x & 1;                  // chunk id (0/1)
    int i    = blockIdx.x * (TB / 2) + gidx;     // node id

    const uint4* hb = (const uint4*)((FOUT == 15) ? sc_h() : sc_g());
    const int* csr = sc_csr();
    float di = 0.f;

    if (i < n) {
        float acc[8];
        #pragma unroll
        for (int t = 0; t < 8; t++) acc[t] = 0.f;

        int beg = sc_row()[i], end = sc_row()[i + 1];
        for (int j = beg; j < end; j++) {
            int s = __ldcs(&csr[j]);             // broadcast across the pair
            acc8(acc, hb[(size_t)s * 2 + c]);
        }
        acc8(acc, hb[(size_t)i * 2 + c]);        // self-loop

        di = sc_dis()[i];
        int k0 = c * 8;
        #pragma unroll
        for (int t = 0; t < 8; t++)
            ysh[gidx][k0 + t] = fmaxf(acc[t] * di + bs[k0 + t], 0.f);
    }
    __syncthreads();

    if (i < n) {
        if (FOUT == 15) {
            // lane c computes output columns c*8 .. c*8+7 (col 15 pad -> 0)
            int j0 = c * 8;
            float o[8];
            #pragma unroll
            for (int t = 0; t < 8; t++) o[t] = 0.f;
            #pragma unroll
            for (int k = 0; k < 15; k++) {
                float yk = ysh[gidx][k];
                #pragma unroll
                for (int t = 0; t < 8; t++)
                    o[t] += yk * Ws[k * 16 + j0 + t];
            }
            #pragma unroll
            for (int t = 0; t < 8; t++) o[t] *= di;
            ((uint4*)sc_g())[(size_t)i * 2 + c] = pack8(o);
        } else {
            // lane c computes output columns c*2, c*2+1 of the 15x4 GEMM
            int j0 = c * 2;
            float o0 = 0.f, o1 = 0.f;
            #pragma unroll
            for (int k = 0; k < 15; k++) {
                float yk = ysh[gidx][k];
                o0 += yk * Ws[k * 4 + j0 + 0];
                o1 += yk * Ws[k * 4 + j0 + 1];
            }
            float2* outp = (float2*)(sc_h3() + (size_t)i * 4 + j0);
            *outp = make_float2(o0 * di, o1 * di);
        }
    }
}

// ---------------- final layer aggregation (fp32, 16B rows) -------------------
__global__ void __launch_bounds__(TB)
k_agg_final(const float* __restrict__ bias, float* __restrict__ out, int n) {
    int i = blockIdx.x * blockDim.x + threadIdx.x;
    if (i >= n) return;
    const float4* hb = (const float4*)sc_h3();
    const int* csr = sc_csr();
    float4 a = make_float4(0.f, 0.f, 0.f, 0.f);
    int beg = sc_row()[i], end = sc_row()[i + 1];
    for (int j = beg; j < end; j++) {
        int s = __ldcs(&csr[j]);
        float4 v = hb[s];
        a.x += v.x; a.y += v.y; a.z += v.z; a.w += v.w;
    }
    float4 v = hb[i];   // self-loop
    a.x += v.x; a.y += v.y; a.z += v.z; a.w += v.w;
    float di = sc_dis()[i];
    float b0 = bias[0], b1 = bias[1], b2 = bias[2], b3 = bias[3];
    ((float4*)out)[i] = make_float4(a.x * di + b0, a.y * di + b1,
                                    a.z * di + b2, a.w * di + b3);
}

// ---------------- launch ------------------------------------------------------
extern "C" void kernel_launch(void* const* d_in, const int* in_sizes, int n_in,
                              void* d_out, int out_size) {
    const float* x = nullptr; const void* ei = nullptr;
    const float* W1 = nullptr; const float* W2 = nullptr;
    const float* b1 = nullptr; const float* b2 = nullptr;
    const float* W3 = nullptr; const float* b3 = nullptr;
    long long E_ll = 0;
    for (int i = 0; i < n_in; i++) {
        long long sz = in_sizes[i];
        if (sz == 7500000)            x = (const float*)d_in[i];
        else if (sz == 32000000)    { ei = d_in[i]; E_ll = sz / 2; }
        else if (sz == 225)         { if (!W1) W1 = (const float*)d_in[i]; else W2 = (const float*)d_in[i]; }
        else if (sz == 15)          { if (!b1) b1 = (const float*)d_in[i]; else b2 = (const float*)d_in[i]; }
        else if (sz == 60)            W3 = (const float*)d_in[i];
        else if (sz == 4)             b3 = (const float*)d_in[i];
    }
    if (!x)  x  = (const float*)d_in[0];
    if (!ei) { ei = d_in[1]; E_ll = in_sizes[1] / 2; }
    if (!W1) W1 = (const float*)d_in[3];
    if (!b1) b1 = (const float*)d_in[4];
    if (!W2) W2 = (const float*)d_in[5];
    if (!b2) b2 = (const float*)d_in[6];
    if (!W3) W3 = (const float*)d_in[7];
    if (!b3) b3 = (const float*)d_in[8];

    float* out = (float*)d_out;
    int n = NN;
    int E = (int)E_ll;

    int gbN  = (n + TB - 1) / TB;
    int gbE  = (E + TB - 1) / TB;
    int nb   = (n + 1023) / 1024;
    int gbN2 = (n + (TB / 2) - 1) / (TB / 2);   // 2 lanes per node

    k_zero<<<gbN, TB>>>((const int*)ei, n);
    k_hist<<<gbE, TB>>>(ei, E);
    k_scan_block<<<nb, 1024>>>(n);
    k_scan_top<<<1, 1024>>>(nb, n);
    k_finish<<<gbN, TB>>>(n);
    k_scatter<<<gbE, TB>>>(ei, E);

    k_t1<<<gbN, TB>>>(x, W1, n);
    k_agg2<15><<<gbN2, TB>>>(b1, W2, n);
    k_agg2<4><<<gbN2, TB>>>(b2, W3, n);
    k_agg_final<<<gbN, TB>>>(b3, out, n);
}